// round 2
// baseline (speedup 1.0000x reference)
#include <cuda_runtime.h>

// ---------------- problem constants ----------------
#define M_NODES 50000
#define E_EDGES 600000
#define IN_CH   300
#define HID     128
#define NGRAPH  128
#define NF      (M_NODES * HID)   // 6,400,000

// ---------------- scratch (static device memory; no allocs) ----------------
// layout: xl[NF] | self[NF] | agg[NF] | colsum[128] | colsumsq[128] | h[NF]
//         | deg[M] | pooled[16384] | cnt[128] | scale[128] | shift[128]
__device__ __align__(16) float g_scratch[4 * NF + 256 + M_NODES + 16384 + 128 + 256];

// ---------------- helpers ----------------
__device__ __forceinline__ void red_add_v4(float* addr, float4 v) {
    asm volatile("red.global.add.v4.f32 [%0], {%1, %2, %3, %4};"
                 :: "l"(addr), "f"(v.x), "f"(v.y), "f"(v.z), "f"(v.w)
                 : "memory");
}

// ---------------- zero kernels ----------------
__global__ void zero4_kernel(float4* __restrict__ p, int n4) {
    int i = blockIdx.x * blockDim.x + threadIdx.x;
    if (i < n4) p[i] = make_float4(0.f, 0.f, 0.f, 0.f);
}

// ---------------- degree ----------------
__global__ void deg_kernel(const int* __restrict__ ei, float* __restrict__ deg, int E) {
    int e = blockIdx.x * blockDim.x + threadIdx.x;
    if (e < E) atomicAdd(&deg[ei[E + e]], 1.0f);
}

// ---------------- SGEMM: C = A[MxK] @ B[Kx128], dual-B via blockIdx.y ----------------
#define BM 128
#define BN 128
#define BK 8
#define TM 8
#define TN 8

__global__ void __launch_bounds__(256)
sgemm_dual(const float* __restrict__ A,
           const float* __restrict__ B0, const float* __restrict__ B1,
           float* __restrict__ C0, float* __restrict__ C1,
           int M, int K)
{
    const float* B = blockIdx.y ? B1 : B0;
    float* C = blockIdx.y ? C1 : C0;
    const int mBase = blockIdx.x * BM;

    __shared__ float As[BK][BM];
    __shared__ float Bs[BK][BN];

    const int tid  = threadIdx.x;
    const int aRow = tid >> 1;            // 0..127
    const int aCol = (tid & 1) * 4;       // 0 or 4
    const int bRow = tid >> 5;            // 0..7
    const int bCol = (tid & 31) << 2;     // 0..124
    const int tr   = (tid >> 4) * TM;     // 0..120
    const int tc   = (tid & 15) * TN;     // 0..120

    float acc[TM][TN] = {};
    float ra[TM], rb[TN];

    for (int k0 = 0; k0 < K; k0 += BK) {
        // A tile (128 x 8), stored transposed As[k][m]
        {
            int gr = mBase + aRow;
            float4 v = make_float4(0.f, 0.f, 0.f, 0.f);
            if (gr < M) {
                if (k0 + aCol + 3 < K) {
                    v = *reinterpret_cast<const float4*>(A + (long long)gr * K + k0 + aCol);
                } else {
                    float t[4];
                    #pragma unroll
                    for (int i = 0; i < 4; i++)
                        t[i] = (k0 + aCol + i < K) ? A[(long long)gr * K + k0 + aCol + i] : 0.f;
                    v = make_float4(t[0], t[1], t[2], t[3]);
                }
            }
            As[aCol + 0][aRow] = v.x;
            As[aCol + 1][aRow] = v.y;
            As[aCol + 2][aRow] = v.z;
            As[aCol + 3][aRow] = v.w;
        }
        // B tile (8 x 128)
        {
            float4 v = make_float4(0.f, 0.f, 0.f, 0.f);
            if (k0 + bRow < K)
                v = *reinterpret_cast<const float4*>(B + (long long)(k0 + bRow) * BN + bCol);
            *reinterpret_cast<float4*>(&Bs[bRow][bCol]) = v;
        }
        __syncthreads();

        #pragma unroll
        for (int kk = 0; kk < BK; kk++) {
            #pragma unroll
            for (int i = 0; i < TM; i++) ra[i] = As[kk][tr + i];
            #pragma unroll
            for (int j = 0; j < TN; j++) rb[j] = Bs[kk][tc + j];
            #pragma unroll
            for (int i = 0; i < TM; i++)
                #pragma unroll
                for (int j = 0; j < TN; j++)
                    acc[i][j] = fmaf(ra[i], rb[j], acc[i][j]);
        }
        __syncthreads();
    }

    #pragma unroll
    for (int i = 0; i < TM; i++) {
        int gr = mBase + tr + i;
        if (gr < M) {
            #pragma unroll
            for (int j = 0; j < TN; j += 4) {
                *reinterpret_cast<float4*>(C + (long long)gr * HID + tc + j) =
                    make_float4(acc[i][j], acc[i][j + 1], acc[i][j + 2], acc[i][j + 3]);
            }
        }
    }
}

// ---------------- edge scatter: agg[dst] += xl[src]  (warp per edge) ----------------
__global__ void scatter_kernel(const float* __restrict__ xl,
                               const int* __restrict__ ei,
                               float* __restrict__ agg, int E)
{
    int warp = (blockIdx.x * blockDim.x + threadIdx.x) >> 5;
    int lane = threadIdx.x & 31;
    if (warp >= E) return;
    int s = ei[warp];
    int d = ei[E + warp];
    float4 v = reinterpret_cast<const float4*>(xl)[s * 32 + lane];
    red_add_v4(agg + (long long)d * HID + lane * 4, v);
}

// ---------------- combine: h = agg/deg + self + b, accumulate BN stats ----------------
#define ROWS_PB 64
__global__ void combine_kernel(const float* __restrict__ agg,
                               const float* __restrict__ self,
                               const float* __restrict__ bias,
                               const float* __restrict__ deg,
                               float* __restrict__ h,
                               float* __restrict__ colsum,
                               float* __restrict__ colsumsq,
                               int M)
{
    int col = threadIdx.x;   // 0..127
    int r0 = blockIdx.x * ROWS_PB;
    int r1 = min(r0 + ROWS_PB, M);
    float b = bias[col];
    float s = 0.f, s2 = 0.f;
    for (int r = r0; r < r1; r++) {
        float dg = fmaxf(deg[r], 1.0f);
        float v = agg[(long long)r * HID + col] / dg + self[(long long)r * HID + col] + b;
        h[(long long)r * HID + col] = v;
        s += v; s2 += v * v;
    }
    atomicAdd(&colsum[col], s);
    atomicAdd(&colsumsq[col], s2);
}

// ---------------- BN finalize: scale/shift per column ----------------
__global__ void bn_finalize(const float* __restrict__ colsum,
                            const float* __restrict__ colsumsq,
                            const float* __restrict__ gamma,
                            const float* __restrict__ beta,
                            float* __restrict__ scale,
                            float* __restrict__ shift, int M)
{
    int c = threadIdx.x;
    float invM = 1.0f / (float)M;
    float mu = colsum[c] * invM;
    float var = colsumsq[c] * invM - mu * mu;
    float rs = rsqrtf(var + 1e-5f);
    float sc = rs * gamma[c];
    scale[c] = sc;
    shift[c] = beta[c] - mu * sc;
}

// ---------------- BN apply + relu (in place, float4) ----------------
__global__ void bn_apply(float4* __restrict__ h,
                         const float* __restrict__ scale,
                         const float* __restrict__ shift, int n4)
{
    int i = blockIdx.x * blockDim.x + threadIdx.x;
    if (i >= n4) return;
    int c = (i & 31) * 4;   // column of first element
    float4 v = h[i];
    v.x = fmaxf(v.x * scale[c + 0] + shift[c + 0], 0.f);
    v.y = fmaxf(v.y * scale[c + 1] + shift[c + 1], 0.f);
    v.z = fmaxf(v.z * scale[c + 2] + shift[c + 2], 0.f);
    v.w = fmaxf(v.w * scale[c + 3] + shift[c + 3], 0.f);
    h[i] = v;
}

// ---------------- pool: pooled[batch[n]] += h[n]; cnt[g] += 1 ----------------
__global__ void pool_kernel(const float* __restrict__ h,
                            const int* __restrict__ batch,
                            float* __restrict__ pooled,
                            float* __restrict__ cnt, int M)
{
    int warp = (blockIdx.x * blockDim.x + threadIdx.x) >> 5;
    int lane = threadIdx.x & 31;
    if (warp >= M) return;
    int g = batch[warp];
    float4 v = reinterpret_cast<const float4*>(h)[warp * 32 + lane];
    red_add_v4(pooled + (long long)g * HID + lane * 4, v);
    if (lane == 0) atomicAdd(&cnt[g], 1.0f);
}

// ---------------- head: hg = pooled/cnt; out = hg @ Wc + bc ----------------
// mode: 0 = [logits(256) | hg(16384)], 1 = logits only, 2 = hg only
__global__ void head_kernel(const float* __restrict__ pooled,
                            const float* __restrict__ cnt,
                            const float* __restrict__ Wc,
                            const float* __restrict__ bc,
                            float* __restrict__ out, int mode)
{
    int g = threadIdx.x;   // 0..127
    float c = fmaxf(cnt[g], 1.f);
    float inv = 1.0f / c;
    float a0 = bc[0], a1 = bc[1];
    float* hg_out = (mode == 0) ? (out + 2 * NGRAPH) : out;
    for (int k = 0; k < HID; k++) {
        float v = pooled[g * HID + k] * inv;
        if (mode != 1) hg_out[g * HID + k] = v;
        a0 = fmaf(v, Wc[k * 2 + 0], a0);
        a1 = fmaf(v, Wc[k * 2 + 1], a1);
    }
    if (mode != 2) {
        out[g * 2 + 0] = a0;
        out[g * 2 + 1] = a1;
    }
}

// ---------------- launcher ----------------
extern "C" void kernel_launch(void* const* d_in, const int* in_sizes, int n_in,
                              void* d_out, int out_size)
{
    const float* x     = (const float*)d_in[0];
    const int*   ei    = (const int*)d_in[1];     // int32: JAX x64 disabled
    const int*   batch = (const int*)d_in[2];

    const float* Wl[3] = { (const float*)d_in[3],  (const float*)d_in[8],  (const float*)d_in[13] };
    const float* Wr[3] = { (const float*)d_in[4],  (const float*)d_in[9],  (const float*)d_in[14] };
    const float* bi[3] = { (const float*)d_in[5],  (const float*)d_in[10], (const float*)d_in[15] };
    const float* ga[3] = { (const float*)d_in[6],  (const float*)d_in[11], (const float*)d_in[16] };
    const float* be[3] = { (const float*)d_in[7],  (const float*)d_in[12], (const float*)d_in[17] };
    const float* Wc = (const float*)d_in[18];
    const float* bc = (const float*)d_in[19];

    float* base = nullptr;
    cudaGetSymbolAddress((void**)&base, g_scratch);

    float* xl       = base;
    float* self     = xl + NF;
    float* agg      = self + NF;
    float* colsum   = agg + NF;        // contiguous with agg for fused zeroing
    float* colsumsq = colsum + HID;
    float* h        = colsumsq + HID;
    float* deg      = h + NF;
    float* pooled   = deg + M_NODES;
    float* cnt      = pooled + NGRAPH * HID;   // contiguous with pooled
    float* scale    = cnt + NGRAPH;
    float* shift    = scale + HID;

    const int M = M_NODES, E = E_EDGES;
    float* out = (float*)d_out;

    // output layout mode (defensive): expected 16640 = [out(256) | hg(16384)]
    int mode = 0;
    if (out_size < 16640) mode = (out_size >= 16384) ? 2 : 1;

    // deg (once; reused for all 3 layers), pooled+cnt zeroing
    {
        int n4 = M / 4;  // 12500
        zero4_kernel<<<(n4 + 255) / 256, 256>>>((float4*)deg, n4);
        int p4 = (NGRAPH * HID + NGRAPH) / 4;  // 4128
        zero4_kernel<<<(p4 + 255) / 256, 256>>>((float4*)pooled, p4);
        deg_kernel<<<(E + 255) / 256, 256>>>(ei, deg, E);
    }

    const float* Ain = x;
    int K = IN_CH;
    for (int l = 0; l < 3; l++) {
        dim3 grid((M + BM - 1) / BM, 2);
        sgemm_dual<<<grid, 256>>>(Ain, Wl[l], Wr[l], xl, self, M, K);

        int z4 = (NF + 256) / 4;  // agg + colsum + colsumsq
        zero4_kernel<<<(z4 + 255) / 256, 256>>>((float4*)agg, z4);

        scatter_kernel<<<(E * 32 + 255) / 256, 256>>>(xl, ei, agg, E);

        combine_kernel<<<(M + ROWS_PB - 1) / ROWS_PB, HID>>>(agg, self, bi[l], deg,
                                                             h, colsum, colsumsq, M);
        bn_finalize<<<1, HID>>>(colsum, colsumsq, ga[l], be[l], scale, shift, M);

        int n4 = NF / 4;
        bn_apply<<<(n4 + 255) / 256, 256>>>((float4*)h, scale, shift, n4);

        Ain = h;
        K = HID;
    }

    pool_kernel<<<(M * 32 + 255) / 256, 256>>>(h, batch, pooled, cnt, M);
    head_kernel<<<1, NGRAPH>>>(pooled, cnt, Wc, bc, out, mode);
}

// round 4
// speedup vs baseline: 1.0102x; 1.0102x over previous
#include <cuda_runtime.h>
#include <cstdint>

// ---------------- problem constants ----------------
#define M_NODES 50000
#define E_EDGES 600000
#define IN_CH   300
#define HID     128
#define NGRAPH  128
#define NF      (M_NODES * HID)   // 6,400,000

// ---------------- scratch (static device memory; no allocs) ----------------
__device__ __align__(16) float g_scratch[4 * NF + 256 + M_NODES + 16384 + 128 + 256];

// ---------------- helpers ----------------
__device__ __forceinline__ void red_add_v4(float* addr, float4 v) {
    asm volatile("red.global.add.v4.f32 [%0], {%1, %2, %3, %4};"
                 :: "l"(addr), "f"(v.x), "f"(v.y), "f"(v.z), "f"(v.w) : "memory");
}
__device__ __forceinline__ uint32_t tf32_rna(float x) {
    uint32_t u;
    asm("cvt.rna.tf32.f32 %0, %1;" : "=r"(u) : "f"(x));
    return u;
}
__device__ __forceinline__ void mma_tf32(float c[4],
                                         uint32_t a0, uint32_t a1, uint32_t a2, uint32_t a3,
                                         uint32_t b0, uint32_t b1) {
    asm volatile(
        "mma.sync.aligned.m16n8k8.row.col.f32.tf32.tf32.f32 "
        "{%0,%1,%2,%3}, {%4,%5,%6,%7}, {%8,%9}, {%0,%1,%2,%3};"
        : "+f"(c[0]), "+f"(c[1]), "+f"(c[2]), "+f"(c[3])
        : "r"(a0), "r"(a1), "r"(a2), "r"(a3), "r"(b0), "r"(b1));
}

// ---------------- TF32x3 tensor-core GEMM: C = A[MxK] @ B[Kx128] ----------------
// dual-B via blockIdx.y (B0->C0, B1->C1). BM=128, BN=128, BK=16.
// 3xTF32: a = hi + lo (both tf32); D += Ah*Bh + Ah*Bl + Al*Bh.
#define LDT 132   // padded k-major row stride (floats): bank = (4k + m) % 32, conflict-free

__global__ void __launch_bounds__(256)
gemm_tf32_mma(const float* __restrict__ A,
              const float* __restrict__ B0, const float* __restrict__ B1,
              float* __restrict__ C0, float* __restrict__ C1,
              int M, int K)
{
    __shared__ uint32_t Ah[16 * LDT], Al[16 * LDT];
    __shared__ uint32_t Bh[16 * LDT], Bl[16 * LDT];

    const float* B = blockIdx.y ? B1 : B0;
    float* C = blockIdx.y ? C1 : C0;
    const int mBase = blockIdx.x * 128;

    const int tid  = threadIdx.x;
    const int wid  = tid >> 5;
    const int lane = tid & 31;
    const int quad = lane >> 2;     // 0..7
    const int tq   = lane & 3;      // 0..3
    const int m0   = (wid & 3) * 32;     // warp M offset (4 warps along M)
    const int n0   = (wid >> 2) * 64;    // warp N offset (2 warps along N)

    float acc[2][8][4];
    #pragma unroll
    for (int i = 0; i < 2; i++)
        #pragma unroll
        for (int j = 0; j < 8; j++)
            #pragma unroll
            for (int q = 0; q < 4; q++) acc[i][j][q] = 0.f;

    const int nT = (K + 15) / 16;

    for (int t = 0; t < nT; t++) {
        const int k0 = t * 16;
        __syncthreads();

        // ---- fill A tile: [128 rows x 16 k] -> Ah/Al[k][m] ----
        #pragma unroll
        for (int i = 0; i < 2; i++) {
            int idx = tid + i * 256;          // 0..511 float4 slots
            int r   = idx >> 2;               // 0..127
            int c4  = (idx & 3) * 4;          // 0,4,8,12
            int gr  = mBase + r;
            float4 v = make_float4(0.f, 0.f, 0.f, 0.f);
            if (gr < M && k0 + c4 + 4 <= K)
                v = *reinterpret_cast<const float4*>(A + (size_t)gr * K + k0 + c4);
            float f[4] = {v.x, v.y, v.z, v.w};
            #pragma unroll
            for (int j = 0; j < 4; j++) {
                uint32_t hi = tf32_rna(f[j]);
                float res = f[j] - __uint_as_float(hi);
                Ah[(c4 + j) * LDT + r] = hi;
                Al[(c4 + j) * LDT + r] = tf32_rna(res);
            }
        }
        // ---- fill B tile: [16 k x 128 n] -> Bh/Bl[k][n] ----
        #pragma unroll
        for (int i = 0; i < 2; i++) {
            int idx = tid + i * 256;
            int k   = idx >> 5;               // 0..15
            int c4  = (idx & 31) * 4;         // 0..124
            float4 v = make_float4(0.f, 0.f, 0.f, 0.f);
            if (k0 + k < K)
                v = *reinterpret_cast<const float4*>(B + (size_t)(k0 + k) * HID + c4);
            float f[4] = {v.x, v.y, v.z, v.w};
            #pragma unroll
            for (int j = 0; j < 4; j++) {
                uint32_t hi = tf32_rna(f[j]);
                float res = f[j] - __uint_as_float(hi);
                Bh[k * LDT + c4 + j] = hi;
                Bl[k * LDT + c4 + j] = tf32_rna(res);
            }
        }
        __syncthreads();

        // ---- compute: 2 k-steps of m16n8k8 ----
        #pragma unroll
        for (int ks = 0; ks < 2; ks++) {
            const int kk = ks * 8;
            const int kr0 = (kk + tq) * LDT;
            const int kr1 = (kk + 4 + tq) * LDT;

            uint32_t ah[2][4], al[2][4];
            #pragma unroll
            for (int mi = 0; mi < 2; mi++) {
                int mr = m0 + mi * 16 + quad;
                ah[mi][0] = Ah[kr0 + mr];     al[mi][0] = Al[kr0 + mr];
                ah[mi][1] = Ah[kr0 + mr + 8]; al[mi][1] = Al[kr0 + mr + 8];
                ah[mi][2] = Ah[kr1 + mr];     al[mi][2] = Al[kr1 + mr];
                ah[mi][3] = Ah[kr1 + mr + 8]; al[mi][3] = Al[kr1 + mr + 8];
            }
            uint32_t bh[8][2], bl[8][2];
            #pragma unroll
            for (int ni = 0; ni < 8; ni++) {
                int nc = n0 + ni * 8 + quad;
                bh[ni][0] = Bh[kr0 + nc]; bh[ni][1] = Bh[kr1 + nc];
                bl[ni][0] = Bl[kr0 + nc]; bl[ni][1] = Bl[kr1 + nc];
            }
            #pragma unroll
            for (int mi = 0; mi < 2; mi++)
                #pragma unroll
                for (int ni = 0; ni < 8; ni++) {
                    mma_tf32(acc[mi][ni], ah[mi][0], ah[mi][1], ah[mi][2], ah[mi][3],
                             bh[ni][0], bh[ni][1]);
                    mma_tf32(acc[mi][ni], ah[mi][0], ah[mi][1], ah[mi][2], ah[mi][3],
                             bl[ni][0], bl[ni][1]);
                    mma_tf32(acc[mi][ni], al[mi][0], al[mi][1], al[mi][2], al[mi][3],
                             bh[ni][0], bh[ni][1]);
                }
        }
    }

    // ---- epilogue ----
    #pragma unroll
    for (int mi = 0; mi < 2; mi++) {
        int r0 = mBase + m0 + mi * 16 + quad;
        #pragma unroll
        for (int ni = 0; ni < 8; ni++) {
            int col = n0 + ni * 8 + tq * 2;
            if (r0 < M)
                *reinterpret_cast<float2*>(C + (size_t)r0 * HID + col) =
                    make_float2(acc[mi][ni][0], acc[mi][ni][1]);
            if (r0 + 8 < M)
                *reinterpret_cast<float2*>(C + (size_t)(r0 + 8) * HID + col) =
                    make_float2(acc[mi][ni][2], acc[mi][ni][3]);
        }
    }
}

// ---------------- zero kernels ----------------
__global__ void zero4_kernel(float4* __restrict__ p, int n4) {
    int i = blockIdx.x * blockDim.x + threadIdx.x;
    if (i < n4) p[i] = make_float4(0.f, 0.f, 0.f, 0.f);
}

// ---------------- degree ----------------
__global__ void deg_kernel(const int* __restrict__ ei, float* __restrict__ deg, int E) {
    int e = blockIdx.x * blockDim.x + threadIdx.x;
    if (e < E) atomicAdd(&deg[ei[E + e]], 1.0f);
}

// ---------------- edge scatter: agg[dst] += xl[src]  (warp per edge) ----------------
__global__ void scatter_kernel(const float* __restrict__ xl,
                               const int* __restrict__ ei,
                               float* __restrict__ agg, int E)
{
    int warp = (blockIdx.x * blockDim.x + threadIdx.x) >> 5;
    int lane = threadIdx.x & 31;
    if (warp >= E) return;
    int s = ei[warp];
    int d = ei[E + warp];
    float4 v = reinterpret_cast<const float4*>(xl)[s * 32 + lane];
    red_add_v4(agg + (long long)d * HID + lane * 4, v);
}

// ---------------- combine: h = agg/deg + self + b, accumulate BN stats ----------------
#define ROWS_PB 64
__global__ void combine_kernel(const float* __restrict__ agg,
                               const float* __restrict__ self,
                               const float* __restrict__ bias,
                               const float* __restrict__ deg,
                               float* __restrict__ h,
                               float* __restrict__ colsum,
                               float* __restrict__ colsumsq,
                               int M)
{
    int col = threadIdx.x;   // 0..127
    int r0 = blockIdx.x * ROWS_PB;
    int r1 = min(r0 + ROWS_PB, M);
    float b = bias[col];
    float s = 0.f, s2 = 0.f;
    for (int r = r0; r < r1; r++) {
        float dg = fmaxf(deg[r], 1.0f);
        float v = agg[(long long)r * HID + col] / dg + self[(long long)r * HID + col] + b;
        h[(long long)r * HID + col] = v;
        s += v; s2 += v * v;
    }
    atomicAdd(&colsum[col], s);
    atomicAdd(&colsumsq[col], s2);
}

// ---------------- BN finalize ----------------
__global__ void bn_finalize(const float* __restrict__ colsum,
                            const float* __restrict__ colsumsq,
                            const float* __restrict__ gamma,
                            const float* __restrict__ beta,
                            float* __restrict__ scale,
                            float* __restrict__ shift, int M)
{
    int c = threadIdx.x;
    float invM = 1.0f / (float)M;
    float mu = colsum[c] * invM;
    float var = colsumsq[c] * invM - mu * mu;
    float rs = rsqrtf(var + 1e-5f);
    float sc = rs * gamma[c];
    scale[c] = sc;
    shift[c] = beta[c] - mu * sc;
}

// ---------------- BN apply + relu ----------------
__global__ void bn_apply(float4* __restrict__ h,
                         const float* __restrict__ scale,
                         const float* __restrict__ shift, int n4)
{
    int i = blockIdx.x * blockDim.x + threadIdx.x;
    if (i >= n4) return;
    int c = (i & 31) * 4;
    float4 v = h[i];
    v.x = fmaxf(v.x * scale[c + 0] + shift[c + 0], 0.f);
    v.y = fmaxf(v.y * scale[c + 1] + shift[c + 1], 0.f);
    v.z = fmaxf(v.z * scale[c + 2] + shift[c + 2], 0.f);
    v.w = fmaxf(v.w * scale[c + 3] + shift[c + 3], 0.f);
    h[i] = v;
}

// ---------------- pool ----------------
__global__ void pool_kernel(const float* __restrict__ h,
                            const int* __restrict__ batch,
                            float* __restrict__ pooled,
                            float* __restrict__ cnt, int M)
{
    int warp = (blockIdx.x * blockDim.x + threadIdx.x) >> 5;
    int lane = threadIdx.x & 31;
    if (warp >= M) return;
    int g = batch[warp];
    float4 v = reinterpret_cast<const float4*>(h)[warp * 32 + lane];
    red_add_v4(pooled + (long long)g * HID + lane * 4, v);
    if (lane == 0) atomicAdd(&cnt[g], 1.0f);
}

// ---------------- head ----------------
__global__ void head_kernel(const float* __restrict__ pooled,
                            const float* __restrict__ cnt,
                            const float* __restrict__ Wc,
                            const float* __restrict__ bc,
                            float* __restrict__ out, int mode)
{
    int g = threadIdx.x;
    float c = fmaxf(cnt[g], 1.f);
    float inv = 1.0f / c;
    float a0 = bc[0], a1 = bc[1];
    float* hg_out = (mode == 0) ? (out + 2 * NGRAPH) : out;
    for (int k = 0; k < HID; k++) {
        float v = pooled[g * HID + k] * inv;
        if (mode != 1) hg_out[g * HID + k] = v;
        a0 = fmaf(v, Wc[k * 2 + 0], a0);
        a1 = fmaf(v, Wc[k * 2 + 1], a1);
    }
    if (mode != 2) {
        out[g * 2 + 0] = a0;
        out[g * 2 + 1] = a1;
    }
}

// ---------------- launcher ----------------
extern "C" void kernel_launch(void* const* d_in, const int* in_sizes, int n_in,
                              void* d_out, int out_size)
{
    const float* x     = (const float*)d_in[0];
    const int*   ei    = (const int*)d_in[1];
    const int*   batch = (const int*)d_in[2];

    const float* Wl[3] = { (const float*)d_in[3],  (const float*)d_in[8],  (const float*)d_in[13] };
    const float* Wr[3] = { (const float*)d_in[4],  (const float*)d_in[9],  (const float*)d_in[14] };
    const float* bi[3] = { (const float*)d_in[5],  (const float*)d_in[10], (const float*)d_in[15] };
    const float* ga[3] = { (const float*)d_in[6],  (const float*)d_in[11], (const float*)d_in[16] };
    const float* be[3] = { (const float*)d_in[7],  (const float*)d_in[12], (const float*)d_in[17] };
    const float* Wc = (const float*)d_in[18];
    const float* bc = (const float*)d_in[19];

    float* base = nullptr;
    cudaGetSymbolAddress((void**)&base, g_scratch);

    float* xl       = base;
    float* self     = xl + NF;
    float* agg      = self + NF;
    float* colsum   = agg + NF;
    float* colsumsq = colsum + HID;
    float* h        = colsumsq + HID;
    float* deg      = h + NF;
    float* pooled   = deg + M_NODES;
    float* cnt      = pooled + NGRAPH * HID;
    float* scale    = cnt + NGRAPH;
    float* shift    = scale + HID;

    const int M = M_NODES, E = E_EDGES;
    float* out = (float*)d_out;

    int mode = 0;
    if (out_size < 16640) mode = (out_size >= 16384) ? 2 : 1;

    {
        int n4 = M / 4;
        zero4_kernel<<<(n4 + 255) / 256, 256>>>((float4*)deg, n4);
        int p4 = (NGRAPH * HID + NGRAPH) / 4;
        zero4_kernel<<<(p4 + 255) / 256, 256>>>((float4*)pooled, p4);
        deg_kernel<<<(E + 255) / 256, 256>>>(ei, deg, E);
    }

    const float* Ain = x;
    int K = IN_CH;
    for (int l = 0; l < 3; l++) {
        dim3 grid((M + 127) / 128, 2);
        gemm_tf32_mma<<<grid, 256>>>(Ain, Wl[l], Wr[l], xl, self, M, K);

        int z4 = (NF + 256) / 4;
        zero4_kernel<<<(z4 + 255) / 256, 256>>>((float4*)agg, z4);

        scatter_kernel<<<(E * 32 + 255) / 256, 256>>>(xl, ei, agg, E);

        combine_kernel<<<(M + ROWS_PB - 1) / ROWS_PB, HID>>>(agg, self, bi[l], deg,
                                                             h, colsum, colsumsq, M);
        bn_finalize<<<1, HID>>>(colsum, colsumsq, ga[l], be[l], scale, shift, M);

        int n4 = NF / 4;
        bn_apply<<<(n4 + 255) / 256, 256>>>((float4*)h, scale, shift, n4);

        Ain = h;
        K = HID;
    }

    pool_kernel<<<(M * 32 + 255) / 256, 256>>>(h, batch, pooled, cnt, M);
    head_kernel<<<1, NGRAPH>>>(pooled, cnt, Wc, bc, out, mode);
}

// round 5
// speedup vs baseline: 1.1967x; 1.1845x over previous
#include <cuda_runtime.h>
#include <cstdint>

// ---------------- problem constants ----------------
#define M_NODES 50000
#define E_EDGES 600000
#define IN_CH   300
#define HID     128
#define NGRAPH  128
#define NF      (M_NODES * HID)   // 6,400,000

// ---------------- scratch (static device memory; no allocs) ----------------
__device__ __align__(16) float g_scratch[4 * NF + 256 + M_NODES + 16384 + 128 + 256];

// ---------------- helpers ----------------
__device__ __forceinline__ void red_add_v4(float* addr, float4 v) {
    asm volatile("red.global.add.v4.f32 [%0], {%1, %2, %3, %4};"
                 :: "l"(addr), "f"(v.x), "f"(v.y), "f"(v.z), "f"(v.w) : "memory");
}
__device__ __forceinline__ uint32_t tf32_rna(float x) {
    uint32_t u;
    asm("cvt.rna.tf32.f32 %0, %1;" : "=r"(u) : "f"(x));
    return u;
}
__device__ __forceinline__ void mma_tf32(float c[4],
                                         uint32_t a0, uint32_t a1, uint32_t a2, uint32_t a3,
                                         uint32_t b0, uint32_t b1) {
    asm volatile(
        "mma.sync.aligned.m16n8k8.row.col.f32.tf32.tf32.f32 "
        "{%0,%1,%2,%3}, {%4,%5,%6,%7}, {%8,%9}, {%0,%1,%2,%3};"
        : "+f"(c[0]), "+f"(c[1]), "+f"(c[2]), "+f"(c[3])
        : "r"(a0), "r"(a1), "r"(a2), "r"(a3), "r"(b0), "r"(b1));
}
__device__ __forceinline__ uint32_t smem_u32(const void* p) {
    uint32_t a;
    asm("{ .reg .u64 t; cvta.to.shared.u64 t, %1; cvt.u32.u64 %0, t; }" : "=r"(a) : "l"(p));
    return a;
}
__device__ __forceinline__ void cp_async16(uint32_t dst, const void* src, int nb) {
    asm volatile("cp.async.cg.shared.global [%0], [%1], 16, %2;"
                 :: "r"(dst), "l"(src), "r"(nb) : "memory");
}
__device__ __forceinline__ void cp_commit() {
    asm volatile("cp.async.commit_group;" ::: "memory");
}
__device__ __forceinline__ void cp_wait1() {
    asm volatile("cp.async.wait_group 1;" ::: "memory");
}
__device__ __forceinline__ void cp_wait0() {
    asm volatile("cp.async.wait_group 0;" ::: "memory");
}

// ---------------- pipelined TF32x3 tensor GEMM ----------------
// C = op(A)[MxK] @ B[Kx128];  op(A) = relu(A*scale[k]+shift[k]) if scale!=null.
// dual-B via blockIdx.y. BM=128, BN=128, BK=16. cp.async double buffering.
#define LDA 20    // floats per A smem row  (bank-conflict-free frag loads)
#define LDB 136   // floats per B smem row

__global__ void __launch_bounds__(256, 2)
gemm_tf32_pipe(const float* __restrict__ A,
               const float* __restrict__ B0, const float* __restrict__ B1,
               float* __restrict__ C0, float* __restrict__ C1,
               const float* __restrict__ scale, const float* __restrict__ shift,
               int M, int K)
{
    __shared__ float As[2][128 * LDA];   // raw fp32, [m][k]
    __shared__ float Bs[2][16 * LDB];    // raw fp32, [k][n]

    const float* B = blockIdx.y ? B1 : B0;
    float* C = blockIdx.y ? C1 : C0;
    const int mBase = blockIdx.x * 128;

    const int tid  = threadIdx.x;
    const int wid  = tid >> 5;
    const int lane = tid & 31;
    const int quad = lane >> 2;      // 0..7
    const int tq   = lane & 3;       // 0..3
    const int m0   = (wid & 3) * 32; // warp M offset
    const int n0   = (wid >> 2) * 64;// warp N offset
    const bool bn  = (scale != nullptr);

    // per-thread load slots (constant across tiles)
    const int ar0 = tid >> 2, ac0 = (tid & 3) * 4;            // A slot 0
    const int ar1 = (tid + 256) >> 2, ac1 = ac0;              // A slot 1
    const int bk0 = tid >> 5, bc0 = (tid & 31) * 4;           // B slot 0
    const int bk1 = (tid + 256) >> 5, bc1 = bc0;              // B slot 1

    const uint32_t sAs = smem_u32(&As[0][0]);
    const uint32_t sBs = smem_u32(&Bs[0][0]);

    float acc[2][8][4];
    #pragma unroll
    for (int i = 0; i < 2; i++)
        #pragma unroll
        for (int j = 0; j < 8; j++)
            #pragma unroll
            for (int q = 0; q < 4; q++) acc[i][j][q] = 0.f;

    const int nT = (K + 15) / 16;

    auto issue_tile = [&](int t, int buf) {
        const int k0 = t * 16;
        // A tile: 128 rows x 16k (4 chunks/row)
        {
            int gr = mBase + ar0;
            const float* src = A + (size_t)gr * K + k0 + ac0;
            int nb = (gr < M && (k0 + ac0) < K) ? 16 : 0;
            if (!nb) src = A;
            cp_async16(sAs + (buf * 128 * LDA + ar0 * LDA + ac0) * 4, src, nb);
        }
        {
            int gr = mBase + ar1;
            const float* src = A + (size_t)gr * K + k0 + ac1;
            int nb = (gr < M && (k0 + ac1) < K) ? 16 : 0;
            if (!nb) src = A;
            cp_async16(sAs + (buf * 128 * LDA + ar1 * LDA + ac1) * 4, src, nb);
        }
        // B tile: 16 k-rows x 128 n (32 chunks/row)
        {
            const float* src = B + (size_t)(k0 + bk0) * HID + bc0;
            int nb = (k0 + bk0 < K) ? 16 : 0;
            if (!nb) src = B;
            cp_async16(sBs + (buf * 16 * LDB + bk0 * LDB + bc0) * 4, src, nb);
        }
        {
            const float* src = B + (size_t)(k0 + bk1) * HID + bc1;
            int nb = (k0 + bk1 < K) ? 16 : 0;
            if (!nb) src = B;
            cp_async16(sBs + (buf * 16 * LDB + bk1 * LDB + bc1) * 4, src, nb);
        }
        cp_commit();
    };

    issue_tile(0, 0);

    for (int t = 0; t < nT; t++) {
        const int buf = t & 1;
        if (t + 1 < nT) {
            issue_tile(t + 1, (t + 1) & 1);
            cp_wait1();
        } else {
            cp_wait0();
        }
        __syncthreads();

        const float* Ab = &As[buf][0];
        const float* Bb = &Bs[buf][0];
        const int k0 = t * 16;

        #pragma unroll
        for (int ks = 0; ks < 2; ks++) {
            const int kk = ks * 8;
            // BN params for this thread's two k indices
            float sc0 = 1.f, sh0 = 0.f, sc1 = 1.f, sh1 = 0.f;
            if (bn) {
                int kA = k0 + kk + tq, kB = kA + 4;
                if (kA < K) { sc0 = scale[kA]; sh0 = shift[kA]; }
                if (kB < K) { sc1 = scale[kB]; sh1 = shift[kB]; }
            }
            // A fragments (hi/lo)
            uint32_t ah[2][4], al[2][4];
            #pragma unroll
            for (int mi = 0; mi < 2; mi++) {
                int mr = m0 + mi * 16 + quad;
                float a0 = Ab[mr * LDA + kk + tq];
                float a1 = Ab[(mr + 8) * LDA + kk + tq];
                float a2 = Ab[mr * LDA + kk + 4 + tq];
                float a3 = Ab[(mr + 8) * LDA + kk + 4 + tq];
                if (bn) {
                    a0 = fmaxf(fmaf(a0, sc0, sh0), 0.f);
                    a1 = fmaxf(fmaf(a1, sc0, sh0), 0.f);
                    a2 = fmaxf(fmaf(a2, sc1, sh1), 0.f);
                    a3 = fmaxf(fmaf(a3, sc1, sh1), 0.f);
                }
                ah[mi][0] = tf32_rna(a0); al[mi][0] = tf32_rna(a0 - __uint_as_float(ah[mi][0]));
                ah[mi][1] = tf32_rna(a1); al[mi][1] = tf32_rna(a1 - __uint_as_float(ah[mi][1]));
                ah[mi][2] = tf32_rna(a2); al[mi][2] = tf32_rna(a2 - __uint_as_float(ah[mi][2]));
                ah[mi][3] = tf32_rna(a3); al[mi][3] = tf32_rna(a3 - __uint_as_float(ah[mi][3]));
            }
            // stream B fragments
            #pragma unroll
            for (int ni = 0; ni < 8; ni++) {
                int nc = n0 + ni * 8 + quad;
                float b0 = Bb[(kk + tq) * LDB + nc];
                float b1 = Bb[(kk + 4 + tq) * LDB + nc];
                uint32_t bh0 = tf32_rna(b0), bh1 = tf32_rna(b1);
                uint32_t bl0 = tf32_rna(b0 - __uint_as_float(bh0));
                uint32_t bl1 = tf32_rna(b1 - __uint_as_float(bh1));
                #pragma unroll
                for (int mi = 0; mi < 2; mi++) {
                    mma_tf32(acc[mi][ni], ah[mi][0], ah[mi][1], ah[mi][2], ah[mi][3], bh0, bh1);
                    mma_tf32(acc[mi][ni], ah[mi][0], ah[mi][1], ah[mi][2], ah[mi][3], bl0, bl1);
                    mma_tf32(acc[mi][ni], al[mi][0], al[mi][1], al[mi][2], al[mi][3], bh0, bh1);
                }
            }
        }
        __syncthreads();
    }

    // ---- epilogue ----
    #pragma unroll
    for (int mi = 0; mi < 2; mi++) {
        int r0 = mBase + m0 + mi * 16 + quad;
        #pragma unroll
        for (int ni = 0; ni < 8; ni++) {
            int col = n0 + ni * 8 + tq * 2;
            if (r0 < M)
                *reinterpret_cast<float2*>(C + (size_t)r0 * HID + col) =
                    make_float2(acc[mi][ni][0], acc[mi][ni][1]);
            if (r0 + 8 < M)
                *reinterpret_cast<float2*>(C + (size_t)(r0 + 8) * HID + col) =
                    make_float2(acc[mi][ni][2], acc[mi][ni][3]);
        }
    }
}

// ---------------- zero kernels ----------------
__global__ void zero4_kernel(float4* __restrict__ p, int n4) {
    int i = blockIdx.x * blockDim.x + threadIdx.x;
    if (i < n4) p[i] = make_float4(0.f, 0.f, 0.f, 0.f);
}

// ---------------- degree ----------------
__global__ void deg_kernel(const int* __restrict__ ei, float* __restrict__ deg, int E) {
    int e = blockIdx.x * blockDim.x + threadIdx.x;
    if (e < E) atomicAdd(&deg[ei[E + e]], 1.0f);
}

// ---------------- edge scatter ----------------
__global__ void scatter_kernel(const float* __restrict__ xl,
                               const int* __restrict__ ei,
                               float* __restrict__ agg, int E)
{
    int warp = (blockIdx.x * blockDim.x + threadIdx.x) >> 5;
    int lane = threadIdx.x & 31;
    if (warp >= E) return;
    int s = ei[warp];
    int d = ei[E + warp];
    float4 v = reinterpret_cast<const float4*>(xl)[s * 32 + lane];
    red_add_v4(agg + (long long)d * HID + lane * 4, v);
}

// ---------------- combine: h = agg/deg + self + b, accumulate BN stats ----------------
#define ROWS_PB 64
__global__ void combine_kernel(const float* __restrict__ agg,
                               const float* __restrict__ self,
                               const float* __restrict__ bias,
                               const float* __restrict__ deg,
                               float* __restrict__ h,
                               float* __restrict__ colsum,
                               float* __restrict__ colsumsq,
                               int M)
{
    int col = threadIdx.x;
    int r0 = blockIdx.x * ROWS_PB;
    int r1 = min(r0 + ROWS_PB, M);
    float b = bias[col];
    float s = 0.f, s2 = 0.f;
    for (int r = r0; r < r1; r++) {
        float dg = fmaxf(deg[r], 1.0f);
        float v = agg[(long long)r * HID + col] / dg + self[(long long)r * HID + col] + b;
        h[(long long)r * HID + col] = v;
        s += v; s2 += v * v;
    }
    atomicAdd(&colsum[col], s);
    atomicAdd(&colsumsq[col], s2);
}

// ---------------- BN finalize ----------------
__global__ void bn_finalize(const float* __restrict__ colsum,
                            const float* __restrict__ colsumsq,
                            const float* __restrict__ gamma,
                            const float* __restrict__ beta,
                            float* __restrict__ scale,
                            float* __restrict__ shift, int M)
{
    int c = threadIdx.x;
    float invM = 1.0f / (float)M;
    float mu = colsum[c] * invM;
    float var = colsumsq[c] * invM - mu * mu;
    float rs = rsqrtf(var + 1e-5f);
    float sc = rs * gamma[c];
    scale[c] = sc;
    shift[c] = beta[c] - mu * sc;
}

// ---------------- BN apply + relu (only for final layer before pool) ----------------
__global__ void bn_apply(float4* __restrict__ h,
                         const float* __restrict__ scale,
                         const float* __restrict__ shift, int n4)
{
    int i = blockIdx.x * blockDim.x + threadIdx.x;
    if (i >= n4) return;
    int c = (i & 31) * 4;
    float4 v = h[i];
    v.x = fmaxf(v.x * scale[c + 0] + shift[c + 0], 0.f);
    v.y = fmaxf(v.y * scale[c + 1] + shift[c + 1], 0.f);
    v.z = fmaxf(v.z * scale[c + 2] + shift[c + 2], 0.f);
    v.w = fmaxf(v.w * scale[c + 3] + shift[c + 3], 0.f);
    h[i] = v;
}

// ---------------- pool ----------------
__global__ void pool_kernel(const float* __restrict__ h,
                            const int* __restrict__ batch,
                            float* __restrict__ pooled,
                            float* __restrict__ cnt, int M)
{
    int warp = (blockIdx.x * blockDim.x + threadIdx.x) >> 5;
    int lane = threadIdx.x & 31;
    if (warp >= M) return;
    int g = batch[warp];
    float4 v = reinterpret_cast<const float4*>(h)[warp * 32 + lane];
    red_add_v4(pooled + (long long)g * HID + lane * 4, v);
    if (lane == 0) atomicAdd(&cnt[g], 1.0f);
}

// ---------------- head ----------------
__global__ void head_kernel(const float* __restrict__ pooled,
                            const float* __restrict__ cnt,
                            const float* __restrict__ Wc,
                            const float* __restrict__ bc,
                            float* __restrict__ out, int mode)
{
    int g = threadIdx.x;
    float c = fmaxf(cnt[g], 1.f);
    float inv = 1.0f / c;
    float a0 = bc[0], a1 = bc[1];
    float* hg_out = (mode == 0) ? (out + 2 * NGRAPH) : out;
    for (int k = 0; k < HID; k++) {
        float v = pooled[g * HID + k] * inv;
        if (mode != 1) hg_out[g * HID + k] = v;
        a0 = fmaf(v, Wc[k * 2 + 0], a0);
        a1 = fmaf(v, Wc[k * 2 + 1], a1);
    }
    if (mode != 2) {
        out[g * 2 + 0] = a0;
        out[g * 2 + 1] = a1;
    }
}

// ---------------- launcher ----------------
extern "C" void kernel_launch(void* const* d_in, const int* in_sizes, int n_in,
                              void* d_out, int out_size)
{
    const float* x     = (const float*)d_in[0];
    const int*   ei    = (const int*)d_in[1];
    const int*   batch = (const int*)d_in[2];

    const float* Wl[3] = { (const float*)d_in[3],  (const float*)d_in[8],  (const float*)d_in[13] };
    const float* Wr[3] = { (const float*)d_in[4],  (const float*)d_in[9],  (const float*)d_in[14] };
    const float* bi[3] = { (const float*)d_in[5],  (const float*)d_in[10], (const float*)d_in[15] };
    const float* ga[3] = { (const float*)d_in[6],  (const float*)d_in[11], (const float*)d_in[16] };
    const float* be[3] = { (const float*)d_in[7],  (const float*)d_in[12], (const float*)d_in[17] };
    const float* Wc = (const float*)d_in[18];
    const float* bc = (const float*)d_in[19];

    float* base = nullptr;
    cudaGetSymbolAddress((void**)&base, g_scratch);

    float* xl       = base;
    float* self     = xl + NF;
    float* agg      = self + NF;
    float* colsum   = agg + NF;
    float* colsumsq = colsum + HID;
    float* h        = colsumsq + HID;
    float* deg      = h + NF;
    float* pooled   = deg + M_NODES;
    float* cnt      = pooled + NGRAPH * HID;
    float* scale    = cnt + NGRAPH;
    float* shift    = scale + HID;

    const int M = M_NODES, E = E_EDGES;
    float* out = (float*)d_out;

    int mode = 0;
    if (out_size < 16640) mode = (out_size >= 16384) ? 2 : 1;

    {
        int n4 = M / 4;
        zero4_kernel<<<(n4 + 255) / 256, 256>>>((float4*)deg, n4);
        int p4 = (NGRAPH * HID + NGRAPH) / 4;
        zero4_kernel<<<(p4 + 255) / 256, 256>>>((float4*)pooled, p4);
        deg_kernel<<<(E + 255) / 256, 256>>>(ei, deg, E);
    }

    const float* Ain = x;
    int K = IN_CH;
    for (int l = 0; l < 3; l++) {
        // BN+relu of previous layer fused into this GEMM's A load
        const float* sc = (l == 0) ? nullptr : scale;
        const float* sh = (l == 0) ? nullptr : shift;

        dim3 grid((M + 127) / 128, 2);
        gemm_tf32_pipe<<<grid, 256>>>(Ain, Wl[l], Wr[l], xl, self, sc, sh, M, K);

        int z4 = (NF + 256) / 4;
        zero4_kernel<<<(z4 + 255) / 256, 256>>>((float4*)agg, z4);

        scatter_kernel<<<(E * 32 + 255) / 256, 256>>>(xl, ei, agg, E);

        combine_kernel<<<(M + ROWS_PB - 1) / ROWS_PB, HID>>>(agg, self, bi[l], deg,
                                                             h, colsum, colsumsq, M);
        bn_finalize<<<1, HID>>>(colsum, colsumsq, ga[l], be[l], scale, shift, M);

        Ain = h;
        K = HID;
    }

    // layer-3 BN+relu applied explicitly before pooling
    {
        int n4 = NF / 4;
        bn_apply<<<(n4 + 255) / 256, 256>>>((float4*)h, scale, shift, n4);
    }

    pool_kernel<<<(M * 32 + 255) / 256, 256>>>(h, batch, pooled, cnt, M);
    head_kernel<<<1, NGRAPH>>>(pooled, cnt, Wc, bc, out, mode);
}

// round 6
// speedup vs baseline: 1.3669x; 1.1423x over previous
#include <cuda_runtime.h>
#include <cstdint>

// ---------------- problem constants ----------------
#define M_NODES 50000
#define E_EDGES 600000
#define IN_CH   300
#define HID     128
#define NGRAPH  128
#define NF      (M_NODES * HID)   // 6,400,000
#define WPK_MAX (160 * 128)       // padded packed-weight slots per array

// ---------------- scratch (static device memory; no allocs) ----------------
__device__ __align__(16) float g_scratch[4 * NF + 256 + M_NODES + 16384 + 128 + 256 + 4 * WPK_MAX];

// ---------------- helpers ----------------
__device__ __forceinline__ void red_add_v4(float* addr, float4 v) {
    asm volatile("red.global.add.v4.f32 [%0], {%1, %2, %3, %4};"
                 :: "l"(addr), "f"(v.x), "f"(v.y), "f"(v.z), "f"(v.w) : "memory");
}
__device__ __forceinline__ uint32_t pkbf(float lo, float hi) {
    uint32_t r;
    asm("cvt.rn.bf16x2.f32 %0, %1, %2;" : "=r"(r) : "f"(hi), "f"(lo));
    return r;   // low 16 bits = lo, high = hi
}
__device__ __forceinline__ float bflo(uint32_t p) { return __uint_as_float(p << 16); }
__device__ __forceinline__ float bfhi(uint32_t p) { return __uint_as_float(p & 0xFFFF0000u); }

__device__ __forceinline__ void mma_bf16(float c[4],
                                         uint32_t a0, uint32_t a1, uint32_t a2, uint32_t a3,
                                         uint32_t b0, uint32_t b1) {
    asm volatile(
        "mma.sync.aligned.m16n8k16.row.col.f32.bf16.bf16.f32 "
        "{%0,%1,%2,%3}, {%4,%5,%6,%7}, {%8,%9}, {%0,%1,%2,%3};"
        : "+f"(c[0]), "+f"(c[1]), "+f"(c[2]), "+f"(c[3])
        : "r"(a0), "r"(a1), "r"(a2), "r"(a3), "r"(b0), "r"(b1));
}
__device__ __forceinline__ uint32_t smem_u32(const void* p) {
    uint32_t a;
    asm("{ .reg .u64 t; cvta.to.shared.u64 t, %1; cvt.u32.u64 %0, t; }" : "=r"(a) : "l"(p));
    return a;
}
__device__ __forceinline__ void cp_async16(uint32_t dst, const void* src, int nb) {
    asm volatile("cp.async.cg.shared.global [%0], [%1], 16, %2;"
                 :: "r"(dst), "l"(src), "r"(nb) : "memory");
}
__device__ __forceinline__ void cp_commit() { asm volatile("cp.async.commit_group;" ::: "memory"); }
__device__ __forceinline__ void cp_wait1()  { asm volatile("cp.async.wait_group 1;" ::: "memory"); }
__device__ __forceinline__ void cp_wait0()  { asm volatile("cp.async.wait_group 0;" ::: "memory"); }

// ---------------- weight pre-split: W[K][128] fp32 -> Wh/Wl packed bf16x2 [n][k2] ----------------
__global__ void split_w(const float* __restrict__ W,
                        uint32_t* __restrict__ Wh, uint32_t* __restrict__ Wl,
                        int K, int K2pad)
{
    int i = blockIdx.x * blockDim.x + threadIdx.x;
    if (i >= 128 * K2pad) return;
    int n = i / K2pad, k2 = i % K2pad;
    float w0 = (2 * k2     < K) ? W[(size_t)(2 * k2)     * HID + n] : 0.f;
    float w1 = (2 * k2 + 1 < K) ? W[(size_t)(2 * k2 + 1) * HID + n] : 0.f;
    uint32_t h = pkbf(w0, w1);
    Wh[i] = h;
    Wl[i] = pkbf(w0 - bflo(h), w1 - bfhi(h));
}

// ---------------- pipelined BF16x3 tensor GEMM ----------------
// C = op(A)[MxK] @ B[Kx128];  op(A) = relu(A*scale[k]+shift[k]) if scale!=null.
// B pre-split into bf16 hi/lo packed pairs [n][K2pad]. dual-B via blockIdx.y.
// BM=128, BN=128, BK=16 (one m16n8k16 k-step per tile). cp.async double buffering.
#define LDA   24   // floats per A smem row (float2 frag loads conflict-free)
#define BNP   12   // u32 per B smem n-row (12q+t bank bijection)
#define OFF_A  0
#define OFF_BH (2 * 128 * LDA * 4)            // 24576
#define OFF_BL (OFF_BH + 2 * 128 * BNP * 4)   // 36864
#define SMEM_TOT (OFF_BL + 2 * 128 * BNP * 4) // 49152

__global__ void __launch_bounds__(256, 2)
gemm_bf16_pipe(const float* __restrict__ A,
               const uint32_t* __restrict__ Bh0, const uint32_t* __restrict__ Bl0,
               const uint32_t* __restrict__ Bh1, const uint32_t* __restrict__ Bl1,
               float* __restrict__ C0, float* __restrict__ C1,
               const float* __restrict__ scale, const float* __restrict__ shift,
               int M, int K, int K2pad)
{
    extern __shared__ char smem[];
    const uint32_t sb = smem_u32(smem);

    const uint32_t* BhG = blockIdx.y ? Bh1 : Bh0;
    const uint32_t* BlG = blockIdx.y ? Bl1 : Bl0;
    float* C = blockIdx.y ? C1 : C0;
    const int mBase = blockIdx.x * 128;

    const int tid  = threadIdx.x;
    const int wid  = tid >> 5;
    const int lane = tid & 31;
    const int quad = lane >> 2;      // 0..7
    const int tq   = lane & 3;       // 0..3
    const int m0   = (wid & 3) * 32;
    const int n0   = (wid >> 2) * 64;
    const bool bn  = (scale != nullptr);

    // cp.async slots
    const int ar0 = tid >> 2, ac0 = (tid & 3) * 4;
    const int ar1 = (tid + 256) >> 2, ac1 = ac0;
    const int bn_row = tid >> 1, bn_ch = (tid & 1) * 4;   // B: n row + 16B chunk

    float acc[2][8][4];
    #pragma unroll
    for (int i = 0; i < 2; i++)
        #pragma unroll
        for (int j = 0; j < 8; j++)
            #pragma unroll
            for (int q = 0; q < 4; q++) acc[i][j][q] = 0.f;

    const int nT = (K + 15) / 16;

    auto issue_tile = [&](int t, int buf) {
        const int k0 = t * 16;
        {
            int gr = mBase + ar0;
            const float* src = A + (size_t)gr * K + k0 + ac0;
            int nb = (gr < M && (k0 + ac0) < K) ? 16 : 0;
            if (!nb) src = A;
            cp_async16(sb + OFF_A + (buf * 128 * LDA + ar0 * LDA + ac0) * 4, src, nb);
        }
        {
            int gr = mBase + ar1;
            const float* src = A + (size_t)gr * K + k0 + ac1;
            int nb = (gr < M && (k0 + ac1) < K) ? 16 : 0;
            if (!nb) src = A;
            cp_async16(sb + OFF_A + (buf * 128 * LDA + ar1 * LDA + ac1) * 4, src, nb);
        }
        {
            const uint32_t* srcH = BhG + (size_t)bn_row * K2pad + t * 8 + bn_ch;
            const uint32_t* srcL = BlG + (size_t)bn_row * K2pad + t * 8 + bn_ch;
            uint32_t d = (buf * 128 * BNP + bn_row * BNP + bn_ch) * 4;
            cp_async16(sb + OFF_BH + d, srcH, 16);
            cp_async16(sb + OFF_BL + d, srcL, 16);
        }
        cp_commit();
    };

    issue_tile(0, 0);

    for (int t = 0; t < nT; t++) {
        const int buf = t & 1;
        if (t + 1 < nT) {
            issue_tile(t + 1, (t + 1) & 1);
            cp_wait1();
        } else {
            cp_wait0();
        }
        __syncthreads();

        const float* Ab = reinterpret_cast<const float*>(smem + OFF_A) + buf * 128 * LDA;
        const uint32_t* Bhb = reinterpret_cast<const uint32_t*>(smem + OFF_BH) + buf * 128 * BNP;
        const uint32_t* Blb = reinterpret_cast<const uint32_t*>(smem + OFF_BL) + buf * 128 * BNP;
        const int k0 = t * 16;

        // BN params for this thread's 4 k-columns (2tq, 2tq+1, 2tq+8, 2tq+9)
        float2 scA = make_float2(1.f, 1.f), shA = make_float2(0.f, 0.f);
        float2 scB = make_float2(1.f, 1.f), shB = make_float2(0.f, 0.f);
        if (bn) {
            scA = *reinterpret_cast<const float2*>(scale + k0 + 2 * tq);
            shA = *reinterpret_cast<const float2*>(shift + k0 + 2 * tq);
            scB = *reinterpret_cast<const float2*>(scale + k0 + 2 * tq + 8);
            shB = *reinterpret_cast<const float2*>(shift + k0 + 2 * tq + 8);
        }

        // A fragments (hi/lo bf16x2)
        uint32_t ah[2][4], al[2][4];
        #pragma unroll
        for (int mi = 0; mi < 2; mi++) {
            int mr = m0 + mi * 16 + quad;
            float2 p0 = *reinterpret_cast<const float2*>(Ab + mr * LDA + 2 * tq);
            float2 p1 = *reinterpret_cast<const float2*>(Ab + (mr + 8) * LDA + 2 * tq);
            float2 p2 = *reinterpret_cast<const float2*>(Ab + mr * LDA + 2 * tq + 8);
            float2 p3 = *reinterpret_cast<const float2*>(Ab + (mr + 8) * LDA + 2 * tq + 8);
            if (bn) {
                p0.x = fmaxf(fmaf(p0.x, scA.x, shA.x), 0.f);
                p0.y = fmaxf(fmaf(p0.y, scA.y, shA.y), 0.f);
                p1.x = fmaxf(fmaf(p1.x, scA.x, shA.x), 0.f);
                p1.y = fmaxf(fmaf(p1.y, scA.y, shA.y), 0.f);
                p2.x = fmaxf(fmaf(p2.x, scB.x, shB.x), 0.f);
                p2.y = fmaxf(fmaf(p2.y, scB.y, shB.y), 0.f);
                p3.x = fmaxf(fmaf(p3.x, scB.x, shB.x), 0.f);
                p3.y = fmaxf(fmaf(p3.y, scB.y, shB.y), 0.f);
            }
            ah[mi][0] = pkbf(p0.x, p0.y);
            al[mi][0] = pkbf(p0.x - bflo(ah[mi][0]), p0.y - bfhi(ah[mi][0]));
            ah[mi][1] = pkbf(p1.x, p1.y);
            al[mi][1] = pkbf(p1.x - bflo(ah[mi][1]), p1.y - bfhi(ah[mi][1]));
            ah[mi][2] = pkbf(p2.x, p2.y);
            al[mi][2] = pkbf(p2.x - bflo(ah[mi][2]), p2.y - bfhi(ah[mi][2]));
            ah[mi][3] = pkbf(p3.x, p3.y);
            al[mi][3] = pkbf(p3.x - bflo(ah[mi][3]), p3.y - bfhi(ah[mi][3]));
        }

        // stream B fragments (already split; bare LDS)
        #pragma unroll
        for (int ni = 0; ni < 8; ni++) {
            int nc = n0 + ni * 8 + quad;
            uint32_t bh0 = Bhb[nc * BNP + tq];
            uint32_t bh1 = Bhb[nc * BNP + tq + 4];
            uint32_t bl0 = Blb[nc * BNP + tq];
            uint32_t bl1 = Blb[nc * BNP + tq + 4];
            #pragma unroll
            for (int mi = 0; mi < 2; mi++) {
                mma_bf16(acc[mi][ni], ah[mi][0], ah[mi][1], ah[mi][2], ah[mi][3], bh0, bh1);
                mma_bf16(acc[mi][ni], ah[mi][0], ah[mi][1], ah[mi][2], ah[mi][3], bl0, bl1);
                mma_bf16(acc[mi][ni], al[mi][0], al[mi][1], al[mi][2], al[mi][3], bh0, bh1);
            }
        }
        __syncthreads();
    }

    // ---- epilogue ----
    #pragma unroll
    for (int mi = 0; mi < 2; mi++) {
        int r0 = mBase + m0 + mi * 16 + quad;
        #pragma unroll
        for (int ni = 0; ni < 8; ni++) {
            int col = n0 + ni * 8 + tq * 2;
            if (r0 < M)
                *reinterpret_cast<float2*>(C + (size_t)r0 * HID + col) =
                    make_float2(acc[mi][ni][0], acc[mi][ni][1]);
            if (r0 + 8 < M)
                *reinterpret_cast<float2*>(C + (size_t)(r0 + 8) * HID + col) =
                    make_float2(acc[mi][ni][2], acc[mi][ni][3]);
        }
    }
}

// ---------------- zero kernels ----------------
__global__ void zero4_kernel(float4* __restrict__ p, int n4) {
    int i = blockIdx.x * blockDim.x + threadIdx.x;
    if (i < n4) p[i] = make_float4(0.f, 0.f, 0.f, 0.f);
}

// ---------------- degree ----------------
__global__ void deg_kernel(const int* __restrict__ ei, float* __restrict__ deg, int E) {
    int e = blockIdx.x * blockDim.x + threadIdx.x;
    if (e < E) atomicAdd(&deg[ei[E + e]], 1.0f);
}

// ---------------- edge scatter ----------------
__global__ void scatter_kernel(const float* __restrict__ xl,
                               const int* __restrict__ ei,
                               float* __restrict__ agg, int E)
{
    int warp = (blockIdx.x * blockDim.x + threadIdx.x) >> 5;
    int lane = threadIdx.x & 31;
    if (warp >= E) return;
    int s = ei[warp];
    int d = ei[E + warp];
    float4 v = reinterpret_cast<const float4*>(xl)[s * 32 + lane];
    red_add_v4(agg + (long long)d * HID + lane * 4, v);
}

// ---------------- combine: h = agg/deg + self + b, accumulate BN stats ----------------
#define ROWS_PB 64
__global__ void combine_kernel(const float* __restrict__ agg,
                               const float* __restrict__ self,
                               const float* __restrict__ bias,
                               const float* __restrict__ deg,
                               float* __restrict__ h,
                               float* __restrict__ colsum,
                               float* __restrict__ colsumsq,
                               int M)
{
    int col = threadIdx.x;
    int r0 = blockIdx.x * ROWS_PB;
    int r1 = min(r0 + ROWS_PB, M);
    float b = bias[col];
    float s = 0.f, s2 = 0.f;
    for (int r = r0; r < r1; r++) {
        float dg = fmaxf(deg[r], 1.0f);
        float v = agg[(long long)r * HID + col] / dg + self[(long long)r * HID + col] + b;
        h[(long long)r * HID + col] = v;
        s += v; s2 += v * v;
    }
    atomicAdd(&colsum[col], s);
    atomicAdd(&colsumsq[col], s2);
}

// ---------------- BN finalize ----------------
__global__ void bn_finalize(const float* __restrict__ colsum,
                            const float* __restrict__ colsumsq,
                            const float* __restrict__ gamma,
                            const float* __restrict__ beta,
                            float* __restrict__ scale,
                            float* __restrict__ shift, int M)
{
    int c = threadIdx.x;
    float invM = 1.0f / (float)M;
    float mu = colsum[c] * invM;
    float var = colsumsq[c] * invM - mu * mu;
    float rs = rsqrtf(var + 1e-5f);
    float sc = rs * gamma[c];
    scale[c] = sc;
    shift[c] = beta[c] - mu * sc;
}

// ---------------- BN apply + relu (final layer before pool) ----------------
__global__ void bn_apply(float4* __restrict__ h,
                         const float* __restrict__ scale,
                         const float* __restrict__ shift, int n4)
{
    int i = blockIdx.x * blockDim.x + threadIdx.x;
    if (i >= n4) return;
    int c = (i & 31) * 4;
    float4 v = h[i];
    v.x = fmaxf(v.x * scale[c + 0] + shift[c + 0], 0.f);
    v.y = fmaxf(v.y * scale[c + 1] + shift[c + 1], 0.f);
    v.z = fmaxf(v.z * scale[c + 2] + shift[c + 2], 0.f);
    v.w = fmaxf(v.w * scale[c + 3] + shift[c + 3], 0.f);
    h[i] = v;
}

// ---------------- pool ----------------
__global__ void pool_kernel(const float* __restrict__ h,
                            const int* __restrict__ batch,
                            float* __restrict__ pooled,
                            float* __restrict__ cnt, int M)
{
    int warp = (blockIdx.x * blockDim.x + threadIdx.x) >> 5;
    int lane = threadIdx.x & 31;
    if (warp >= M) return;
    int g = batch[warp];
    float4 v = reinterpret_cast<const float4*>(h)[warp * 32 + lane];
    red_add_v4(pooled + (long long)g * HID + lane * 4, v);
    if (lane == 0) atomicAdd(&cnt[g], 1.0f);
}

// ---------------- head ----------------
__global__ void head_kernel(const float* __restrict__ pooled,
                            const float* __restrict__ cnt,
                            const float* __restrict__ Wc,
                            const float* __restrict__ bc,
                            float* __restrict__ out, int mode)
{
    int g = threadIdx.x;
    float c = fmaxf(cnt[g], 1.f);
    float inv = 1.0f / c;
    float a0 = bc[0], a1 = bc[1];
    float* hg_out = (mode == 0) ? (out + 2 * NGRAPH) : out;
    for (int k = 0; k < HID; k++) {
        float v = pooled[g * HID + k] * inv;
        if (mode != 1) hg_out[g * HID + k] = v;
        a0 = fmaf(v, Wc[k * 2 + 0], a0);
        a1 = fmaf(v, Wc[k * 2 + 1], a1);
    }
    if (mode != 2) {
        out[g * 2 + 0] = a0;
        out[g * 2 + 1] = a1;
    }
}

// ---------------- launcher ----------------
extern "C" void kernel_launch(void* const* d_in, const int* in_sizes, int n_in,
                              void* d_out, int out_size)
{
    const float* x     = (const float*)d_in[0];
    const int*   ei    = (const int*)d_in[1];
    const int*   batch = (const int*)d_in[2];

    const float* Wl[3] = { (const float*)d_in[3],  (const float*)d_in[8],  (const float*)d_in[13] };
    const float* Wr[3] = { (const float*)d_in[4],  (const float*)d_in[9],  (const float*)d_in[14] };
    const float* bi[3] = { (const float*)d_in[5],  (const float*)d_in[10], (const float*)d_in[15] };
    const float* ga[3] = { (const float*)d_in[6],  (const float*)d_in[11], (const float*)d_in[16] };
    const float* be[3] = { (const float*)d_in[7],  (const float*)d_in[12], (const float*)d_in[17] };
    const float* Wc = (const float*)d_in[18];
    const float* bc = (const float*)d_in[19];

    float* base = nullptr;
    cudaGetSymbolAddress((void**)&base, g_scratch);

    float* xl       = base;
    float* self     = xl + NF;
    float* agg      = self + NF;
    float* colsum   = agg + NF;
    float* colsumsq = colsum + HID;
    float* h        = colsumsq + HID;
    float* deg      = h + NF;
    float* pooled   = deg + M_NODES;
    float* cnt      = pooled + NGRAPH * HID;
    float* scale    = cnt + NGRAPH;
    float* shift    = scale + HID;
    uint32_t* pWh0  = (uint32_t*)(shift + HID);
    uint32_t* pWlo0 = pWh0 + WPK_MAX;
    uint32_t* pWh1  = pWlo0 + WPK_MAX;
    uint32_t* pWlo1 = pWh1 + WPK_MAX;

    const int M = M_NODES, E = E_EDGES;
    float* out = (float*)d_out;

    int mode = 0;
    if (out_size < 16640) mode = (out_size >= 16384) ? 2 : 1;

    cudaFuncSetAttribute(gemm_bf16_pipe,
                         cudaFuncAttributeMaxDynamicSharedMemorySize, SMEM_TOT);

    {
        int n4 = M / 4;
        zero4_kernel<<<(n4 + 255) / 256, 256>>>((float4*)deg, n4);
        int p4 = (NGRAPH * HID + NGRAPH) / 4;
        zero4_kernel<<<(p4 + 255) / 256, 256>>>((float4*)pooled, p4);
        deg_kernel<<<(E + 255) / 256, 256>>>(ei, deg, E);
    }

    const float* Ain = x;
    int K = IN_CH;
    for (int l = 0; l < 3; l++) {
        const int K2pad = ((K + 15) / 16) * 8;   // 152 or 64
        {
            int nth = 128 * K2pad;
            split_w<<<(nth + 255) / 256, 256>>>(Wl[l], pWh0, pWlo0, K, K2pad);
            split_w<<<(nth + 255) / 256, 256>>>(Wr[l], pWh1, pWlo1, K, K2pad);
        }

        const float* sc = (l == 0) ? nullptr : scale;
        const float* sh = (l == 0) ? nullptr : shift;

        dim3 grid((M + 127) / 128, 2);
        gemm_bf16_pipe<<<grid, 256, SMEM_TOT>>>(Ain, pWh0, pWlo0, pWh1, pWlo1,
                                                xl, self, sc, sh, M, K, K2pad);

        int z4 = (NF + 256) / 4;
        zero4_kernel<<<(z4 + 255) / 256, 256>>>((float4*)agg, z4);

        scatter_kernel<<<(E * 32 + 255) / 256, 256>>>(xl, ei, agg, E);

        combine_kernel<<<(M + ROWS_PB - 1) / ROWS_PB, HID>>>(agg, self, bi[l], deg,
                                                             h, colsum, colsumsq, M);
        bn_finalize<<<1, HID>>>(colsum, colsumsq, ga[l], be[l], scale, shift, M);

        Ain = h;
        K = HID;
    }

    {
        int n4 = NF / 4;
        bn_apply<<<(n4 + 255) / 256, 256>>>((float4*)h, scale, shift, n4);
    }

    pool_kernel<<<(M * 32 + 255) / 256, 256>>>(h, batch, pooled, cnt, M);
    head_kernel<<<1, NGRAPH>>>(pooled, cnt, Wc, bc, out, mode);
}